// round 3
// baseline (speedup 1.0000x reference)
#include <cuda_runtime.h>
#include <cstdint>

// EmbeddingBag mode='sum':
//   out[b][:] = sum_{i in [offsets[b], offsets[b+1])} W[indices[i]][:]
// W: [TABLE_LEN, 64] f32, indices: [N_IDX] i32, offsets: [N_BAGS] i32.
//
// One warp per bag. Each lane handles 2 of the 64 dims as float2, so a full
// warp load of one embedding row is exactly 256 contiguous bytes (coalesced,
// 2x128B lines). Bag loop unrolled x4 with independent accumulators for MLP.

#define EMB_DIM 64
#define F2_PER_ROW (EMB_DIM / 2)   // 32 float2 per row -> one per lane

__global__ __launch_bounds__(256) void embag_sum_kernel(
    const float2* __restrict__ W2,     // W reinterpreted as float2[TABLE_LEN*32]
    const int*    __restrict__ indices,
    const int*    __restrict__ offsets,
    float2*       __restrict__ out2,   // out as float2[N_BAGS*32]
    int n_idx,
    int n_bags)
{
    const int warp = (blockIdx.x * blockDim.x + threadIdx.x) >> 5;
    const int lane = threadIdx.x & 31;
    if (warp >= n_bags) return;

    const int start = __ldg(&offsets[warp]);
    const int end   = (warp + 1 < n_bags) ? __ldg(&offsets[warp + 1]) : n_idx;

    float2 a0 = make_float2(0.f, 0.f);
    float2 a1 = make_float2(0.f, 0.f);
    float2 a2 = make_float2(0.f, 0.f);
    float2 a3 = make_float2(0.f, 0.f);

    int i = start;
    // Main loop: 4 independent row loads in flight per iteration (MLP=4).
    for (; i + 4 <= end; i += 4) {
        const int r0 = __ldg(&indices[i + 0]);
        const int r1 = __ldg(&indices[i + 1]);
        const int r2 = __ldg(&indices[i + 2]);
        const int r3 = __ldg(&indices[i + 3]);

        const float2 v0 = __ldg(&W2[(size_t)r0 * F2_PER_ROW + lane]);
        const float2 v1 = __ldg(&W2[(size_t)r1 * F2_PER_ROW + lane]);
        const float2 v2 = __ldg(&W2[(size_t)r2 * F2_PER_ROW + lane]);
        const float2 v3 = __ldg(&W2[(size_t)r3 * F2_PER_ROW + lane]);

        a0.x += v0.x; a0.y += v0.y;
        a1.x += v1.x; a1.y += v1.y;
        a2.x += v2.x; a2.y += v2.y;
        a3.x += v3.x; a3.y += v3.y;
    }
    // Tail
    for (; i < end; ++i) {
        const int r = __ldg(&indices[i]);
        const float2 v = __ldg(&W2[(size_t)r * F2_PER_ROW + lane]);
        a0.x += v.x; a0.y += v.y;
    }

    float2 acc;
    acc.x = (a0.x + a1.x) + (a2.x + a3.x);
    acc.y = (a0.y + a1.y) + (a2.y + a3.y);

    out2[(size_t)warp * F2_PER_ROW + lane] = acc;
}

extern "C" void kernel_launch(void* const* d_in, const int* in_sizes, int n_in,
                              void* d_out, int out_size)
{
    // Inputs per metadata order: W (f32), indices (i32), offsets (i32)
    const float2* W2      = (const float2*)d_in[0];
    const int*    indices = (const int*)d_in[1];
    const int*    offsets = (const int*)d_in[2];
    float2*       out2    = (float2*)d_out;

    const int n_idx  = in_sizes[1];
    const int n_bags = in_sizes[2];

    // One warp per bag; 8 warps (256 threads) per block.
    const int warps_per_block = 256 / 32;
    const int blocks = (n_bags + warps_per_block - 1) / warps_per_block;

    embag_sum_kernel<<<blocks, 256>>>(W2, indices, offsets, out2, n_idx, n_bags);
}

// round 7
// speedup vs baseline: 1.0656x; 1.0656x over previous
#include <cuda_runtime.h>
#include <cstdint>

// EmbeddingBag mode='sum' with L2 residency control via 256-bit loads.
//   out[b][:] = sum_{i in [offsets[b], offsets[b+1])} W[indices[i]][:]
//
// Warp per bag. Lane-group g = lane>>3 owns index i+g; each lane loads 8
// dims (32B) with one ld.global.nc.v8.b32 -> one warp-load = 4 rows (1024B).
// Rows < pin_rows use L2::evict_last (stable ~110MB resident set, warm across
// graph replays); others use L2::evict_first (don't pollute the pinned set).
// End of bag: shfl.xor over lane^8 / lane^16 folds the 4 groups; lanes 0-7
// store the 64-dim result as 2x float4.

#define EMB_DIM 64

__device__ __forceinline__ void ld8_last(const float* p, float* v) {
    uint32_t r0,r1,r2,r3,r4,r5,r6,r7;
    asm("ld.global.nc.L2::evict_last.v8.b32 {%0,%1,%2,%3,%4,%5,%6,%7}, [%8];"
        : "=r"(r0),"=r"(r1),"=r"(r2),"=r"(r3),
          "=r"(r4),"=r"(r5),"=r"(r6),"=r"(r7) : "l"(p));
    v[0]=__uint_as_float(r0); v[1]=__uint_as_float(r1);
    v[2]=__uint_as_float(r2); v[3]=__uint_as_float(r3);
    v[4]=__uint_as_float(r4); v[5]=__uint_as_float(r5);
    v[6]=__uint_as_float(r6); v[7]=__uint_as_float(r7);
}
__device__ __forceinline__ void ld8_first(const float* p, float* v) {
    uint32_t r0,r1,r2,r3,r4,r5,r6,r7;
    asm("ld.global.nc.L2::evict_first.v8.b32 {%0,%1,%2,%3,%4,%5,%6,%7}, [%8];"
        : "=r"(r0),"=r"(r1),"=r"(r2),"=r"(r3),
          "=r"(r4),"=r"(r5),"=r"(r6),"=r"(r7) : "l"(p));
    v[0]=__uint_as_float(r0); v[1]=__uint_as_float(r1);
    v[2]=__uint_as_float(r2); v[3]=__uint_as_float(r3);
    v[4]=__uint_as_float(r4); v[5]=__uint_as_float(r5);
    v[6]=__uint_as_float(r6); v[7]=__uint_as_float(r7);
}
__device__ __forceinline__ void ld_row8(const float* __restrict__ W,
                                        int r, int sublane, int pin_rows,
                                        float* v) {
    const float* p = W + (size_t)r * EMB_DIM + sublane * 8;
    if (r < pin_rows) ld8_last(p, v);
    else              ld8_first(p, v);
}

__global__ __launch_bounds__(256) void embag_sum_kernel(
    const float* __restrict__ W,
    const int*   __restrict__ indices,
    const int*   __restrict__ offsets,
    float*       __restrict__ out,
    int n_idx,
    int n_bags,
    int pin_rows)
{
    const int warp    = (blockIdx.x * blockDim.x + threadIdx.x) >> 5;
    const int lane    = threadIdx.x & 31;
    const int grp     = lane >> 3;   // 0..3: which index within a 4-pack
    const int sublane = lane & 7;    // 0..7: which 8-dim slice of the row
    if (warp >= n_bags) return;

    const int start = __ldg(&offsets[warp]);
    const int end   = (warp + 1 < n_bags) ? __ldg(&offsets[warp + 1]) : n_idx;

    float acc0[8], acc1[8];
    #pragma unroll
    for (int k = 0; k < 8; ++k) { acc0[k] = 0.f; acc1[k] = 0.f; }

    int i = start;
    // Main loop: 8 indices per iteration, 2 independent 32B vector loads/lane.
    for (; i + 8 <= end; i += 8) {
        const int ra = __ldg(&indices[i + grp]);
        const int rb = __ldg(&indices[i + 4 + grp]);
        float va[8], vb[8];
        ld_row8(W, ra, sublane, pin_rows, va);
        ld_row8(W, rb, sublane, pin_rows, vb);
        #pragma unroll
        for (int k = 0; k < 8; ++k) { acc0[k] += va[k]; acc1[k] += vb[k]; }
    }
    // 4-wide tail
    if (i + 4 <= end) {
        const int r = __ldg(&indices[i + grp]);
        float v[8];
        ld_row8(W, r, sublane, pin_rows, v);
        #pragma unroll
        for (int k = 0; k < 8; ++k) acc0[k] += v[k];
        i += 4;
    }
    // Final ragged tail (0..3 indices): group-predicated
    {
        const int rem = end - i;
        if (grp < rem) {
            const int r = __ldg(&indices[i + grp]);
            float v[8];
            ld_row8(W, r, sublane, pin_rows, v);
            #pragma unroll
            for (int k = 0; k < 8; ++k) acc1[k] += v[k];
        }
    }

    // Fold the two accumulator sets, then reduce across the 4 lane-groups.
    #pragma unroll
    for (int k = 0; k < 8; ++k) {
        float a = acc0[k] + acc1[k];
        a += __shfl_xor_sync(0xFFFFFFFFu, a, 8);
        a += __shfl_xor_sync(0xFFFFFFFFu, a, 16);
        acc0[k] = a;
    }

    // Lanes 0-7 hold the full sum for dims [lane*8, lane*8+8). Store 2x float4.
    if (lane < 8) {
        float4* o = (float4*)(out + (size_t)warp * EMB_DIM + lane * 8);
        o[0] = make_float4(acc0[0], acc0[1], acc0[2], acc0[3]);
        o[1] = make_float4(acc0[4], acc0[5], acc0[6], acc0[7]);
    }
}

extern "C" void kernel_launch(void* const* d_in, const int* in_sizes, int n_in,
                              void* d_out, int out_size)
{
    const float* W       = (const float*)d_in[0];
    const int*   indices = (const int*)d_in[1];
    const int*   offsets = (const int*)d_in[2];
    float*       out     = (float*)d_out;

    const int n_idx  = in_sizes[1];
    const int n_bags = in_sizes[2];

    const long long table_rows = (long long)in_sizes[0] / EMB_DIM;
    long long pin = (110ll * 1024 * 1024) / (EMB_DIM * sizeof(float));  // rows
    if (pin > table_rows) pin = table_rows;

    const int warps_per_block = 256 / 32;
    const int blocks = (n_bags + warps_per_block - 1) / warps_per_block;

    embag_sum_kernel<<<blocks, 256>>>(W, indices, offsets, out,
                                      n_idx, n_bags, (int)pin);
}